// round 13
// baseline (speedup 1.0000x reference)
#include <cuda_runtime.h>
#include <cuda_fp16.h>
#include <cstdint>

#define BATCH 32768
#define NF 162
#define KPAD 176
#define ACCN 1024
#define XW 2048
#define NB 8
#define NTB 80                 // 64-row tile slots per bucket (capacity 5120 rows)
#define MAXT2 (NB * NTB)       // 640 tiles

// ---------------- scratch ----------------
__device__ __half g_F[(size_t)2 * BATCH * KPAD];
__device__ __half g_X[(size_t)BATCH * XW];
__device__ __half g_Wt[(size_t)KPAD * ACCN];         // W_acc^T k-major, zero-padded
__device__ __half g_W1t[XW * 256];                   // W1^T [k][n]
__device__ float  g_psqt_s[BATCH];
__device__ float  g_psqt_n[BATCH];
__device__ int    g_cnt[NB];                         // zero at load; snapshotted+zeroed by gemm1
__device__ int    g_cnt2[NB];                        // stable copy for gemm2
__device__ int    g_perm[NB * BATCH];

__device__ __forceinline__ uint32_t smem_u32(const void* p) {
    return (uint32_t)__cvta_generic_to_shared(p);
}

// ---------------- prep: tiled transposes + feature packing in one launch ----------------
// blocks [0,192): Wacc transpose (32 j-tiles x 6 k-tiles)
// blocks [192,704): W1 transpose (8 n-tiles x 64 k-tiles)
// blocks [704,...): feature packing, one warp per (side,row)
#define WACC_BLKS 192
#define W1_BLKS 512
#define FEAT_BASE (WACC_BLKS + W1_BLKS)

__global__ void __launch_bounds__(256) prep_kernel(const float* __restrict__ stm,
                                                   const float* __restrict__ nstm,
                                                   const float* __restrict__ Wacc,
                                                   const float* __restrict__ W1) {
    const int bid = blockIdx.x;
    if (bid < FEAT_BASE) {
        __shared__ float s[32][33];
        const int tx = threadIdx.x & 31, ty = threadIdx.x >> 5;   // 32 x 8
        if (bid < WACC_BLKS) {
            const int j0 = (bid & 31) * 32, k0 = (bid >> 5) * 32;
            #pragma unroll
            for (int r = 0; r < 4; ++r) {
                int j = j0 + ty + r * 8, k = k0 + tx;
                s[ty + r * 8][tx] = (k < NF) ? Wacc[(size_t)j * NF + k] : 0.f;
            }
            __syncthreads();
            #pragma unroll
            for (int r = 0; r < 4; ++r) {
                int k = k0 + ty + r * 8;
                if (k < KPAD) g_Wt[(size_t)k * ACCN + j0 + tx] = __float2half_rn(s[tx][ty + r * 8]);
            }
        } else {
            const int q = bid - WACC_BLKS;
            const int n0 = (q & 7) * 32, k0 = (q >> 3) * 32;
            #pragma unroll
            for (int r = 0; r < 4; ++r)
                s[ty + r * 8][tx] = W1[(size_t)(n0 + ty + r * 8) * XW + k0 + tx];
            __syncthreads();
            #pragma unroll
            for (int r = 0; r < 4; ++r)
                g_W1t[(size_t)(k0 + ty + r * 8) * 256 + n0 + tx] =
                    __float2half_rn(s[tx][ty + r * 8]);
        }
        return;
    }
    // feature part
    int warp = ((bid - FEAT_BASE) * 256 + threadIdx.x) >> 5;
    int lane = threadIdx.x & 31;
    if (warp >= 2 * BATCH) return;
    const float2* WaccLast = (const float2*)(Wacc + (size_t)ACCN * NF);
    const bool is_stm = (warp < BATCH);
    const float2* src = (const float2*)(is_stm ? stm + (size_t)warp * NF
                                               : nstm + (size_t)(warp - BATCH) * NF);
    __half2* dst = (__half2*)(g_F + (size_t)warp * KPAD);

    float cnt = 0.f, ps = 0.f;
    #pragma unroll
    for (int it = 0; it < 3; ++it) {
        int p = lane + it * 32;                      // KPAD/2 = 88 pairs
        if (p < 88) {
            float x = 0.f, y = 0.f;
            if (p < 81) {
                float2 v = src[p];
                x = v.x; y = v.y;
                float2 w = WaccLast[p];
                ps += x * w.x + y * w.y;
                cnt += x + y;
            }
            dst[p] = __floats2half2_rn(x, y);
        }
    }
    #pragma unroll
    for (int o = 16; o; o >>= 1) {
        cnt += __shfl_xor_sync(0xffffffffu, cnt, o);
        ps  += __shfl_xor_sync(0xffffffffu, ps,  o);
    }
    if (lane == 0) {
        if (is_stm) {
            int pc = (int)(cnt + 0.5f);
            int b  = pc / 20;
            b = (b > NB - 1) ? NB - 1 : b;
            int pos = atomicAdd(&g_cnt[b], 1);
            g_perm[b * BATCH + pos] = warp;
            g_psqt_s[warp] = ps;
        } else {
            g_psqt_n[warp - BATCH] = ps;
        }
    }
}

// ---------------- GEMM1: proven R3/R6 version + counter snapshot ----------------
#define BSTR 136
#define ASTR 184
#define G1_SMEM ((KPAD * BSTR + 2 * 128 * ASTR) * 2)

__global__ void __launch_bounds__(512) gemm1_kernel(const float* __restrict__ bias) {
    extern __shared__ __half sh[];
    __half* Bs = sh;                       // [176][BSTR]
    __half* As = sh + KPAD * BSTR;         // [2][128][ASTR]

    const int tid  = threadIdx.x;
    const int lane = tid & 31, wid = tid >> 5;
    const int wm = wid & 3, wn = wid >> 2;          // 4x4 warps, warp tile 32x32
    const int n0 = blockIdx.y * 128;
    const int mslot = blockIdx.x;                   // 0..17

    if (blockIdx.x == 0 && blockIdx.y == 0 && tid < NB) {
        g_cnt2[tid] = g_cnt[tid];                   // snapshot for gemm2
        g_cnt[tid] = 0;                             // clean state for next replay
    }

    for (int idx = tid; idx < KPAD * 16; idx += 512) {
        int k = idx >> 4, c = idx & 15;
        asm volatile("cp.async.cg.shared.global [%0], [%1], 16;\n"
                     :: "r"(smem_u32(Bs + k * BSTR + c * 8)),
                        "l"(g_Wt + (size_t)k * ACCN + n0 + c * 8));
    }

    auto loadA = [&](int buf, int mt) {
        const __half* base = g_F + (size_t)mt * 128 * KPAD;
        __half* dst = As + buf * (128 * ASTR);
        #pragma unroll
        for (int it = 0; it < 6; ++it) {
            int idx = tid + it * 512;                // 128 x 22 chunks
            if (idx < 128 * 22) {
                int r = idx / 22, c = idx - r * 22;
                asm volatile("cp.async.cg.shared.global [%0], [%1], 16;\n"
                             :: "r"(smem_u32(dst + r * ASTR + c * 8)),
                                "l"(base + (size_t)r * KPAD + c * 8));
            }
        }
    };

    loadA(0, mslot);
    asm volatile("cp.async.commit_group;\n");
    const int jmax = (512 - mslot + 17) / 18;
    if (jmax > 1) loadA(1, mslot + 18);
    asm volatile("cp.async.commit_group;\n");

    const int g = lane >> 2, t4 = lane & 3;
    int buf = 0;
    for (int j = 0; j < jmax; ++j) {
        const int mt = mslot + j * 18;
        asm volatile("cp.async.wait_group 1;\n");
        __syncthreads();

        float acc[2][4][4];
        #pragma unroll
        for (int i = 0; i < 2; ++i)
            #pragma unroll
            for (int jj = 0; jj < 4; ++jj)
                #pragma unroll
                for (int k = 0; k < 4; ++k) acc[i][jj][k] = 0.f;

        const __half* Ab = As + buf * (128 * ASTR);
        #pragma unroll
        for (int kt = 0; kt < 11; ++kt) {
            uint32_t af[2][4], bf[4][2];
            #pragma unroll
            for (int mf = 0; mf < 2; ++mf) {
                const __half* p = Ab + (wm * 32 + mf * 16 + ((lane >> 3) & 1) * 8 + (lane & 7)) * ASTR
                                     + kt * 16 + (lane >> 4) * 8;
                asm volatile("ldmatrix.sync.aligned.m8n8.x4.shared.b16 {%0,%1,%2,%3}, [%4];\n"
                             : "=r"(af[mf][0]), "=r"(af[mf][1]), "=r"(af[mf][2]), "=r"(af[mf][3])
                             : "r"(smem_u32(p)));
            }
            #pragma unroll
            for (int ng = 0; ng < 2; ++ng) {
                const __half* p = Bs + (kt * 16 + ((lane >> 3) & 1) * 8 + (lane & 7)) * BSTR
                                     + wn * 32 + ng * 16 + (lane >> 4) * 8;
                uint32_t r0, r1, r2, r3;
                asm volatile("ldmatrix.sync.aligned.m8n8.x4.trans.shared.b16 {%0,%1,%2,%3}, [%4];\n"
                             : "=r"(r0), "=r"(r1), "=r"(r2), "=r"(r3) : "r"(smem_u32(p)));
                bf[ng * 2 + 0][0] = r0; bf[ng * 2 + 0][1] = r1;
                bf[ng * 2 + 1][0] = r2; bf[ng * 2 + 1][1] = r3;
            }
            #pragma unroll
            for (int mf = 0; mf < 2; ++mf)
                #pragma unroll
                for (int nf = 0; nf < 4; ++nf)
                    asm volatile(
                        "mma.sync.aligned.m16n8k16.row.col.f32.f16.f16.f32 "
                        "{%0,%1,%2,%3}, {%4,%5,%6,%7}, {%8,%9}, {%0,%1,%2,%3};\n"
                        : "+f"(acc[mf][nf][0]), "+f"(acc[mf][nf][1]),
                          "+f"(acc[mf][nf][2]), "+f"(acc[mf][nf][3])
                        : "r"(af[mf][0]), "r"(af[mf][1]), "r"(af[mf][2]), "r"(af[mf][3]),
                          "r"(bf[nf][0]), "r"(bf[nf][1]));
        }
        __syncthreads();

        if (j + 2 < jmax) loadA(buf, mslot + (j + 2) * 18);
        asm volatile("cp.async.commit_group;\n");

        // epilogue: bias + clip^2 -> g_X
        #pragma unroll
        for (int mf = 0; mf < 2; ++mf) {
            #pragma unroll
            for (int nf = 0; nf < 4; ++nf) {
                const int col = n0 + wn * 32 + nf * 8 + 2 * t4;
                #pragma unroll
                for (int h = 0; h < 2; ++h) {
                    const int row = mt * 128 + wm * 32 + mf * 16 + g + h * 8;
                    float v0 = __saturatef(acc[mf][nf][h * 2 + 0] + bias[col]);     v0 *= v0;
                    float v1 = __saturatef(acc[mf][nf][h * 2 + 1] + bias[col + 1]); v1 *= v1;
                    const size_t off = (row < BATCH)
                        ? (size_t)row * XW + col
                        : (size_t)(row - BATCH) * XW + ACCN + col;
                    *(__half2*)(g_X + off) = __floats2half2_rn(v0, v1);
                }
            }
        }
        buf ^= 1;
    }
}

// ---------------- GEMM2: 64-row tiles, BK=32, 4-stage ring, fused tail ----------------
#define A2STR 40
#define STG_A (64 * A2STR)     // 2560 halves
#define STG_B (32 * A2STR)     // 1280 halves
#define STG_H (STG_A + STG_B)
#define G2_DYN (4 * STG_H * 2) // 30720 bytes; tail overlay (13.9 KB) fits inside

__global__ void __launch_bounds__(256) gemm2_kernel(const float* __restrict__ b1,
                                                    const float* __restrict__ W2,
                                                    const float* __restrict__ b2,
                                                    const float* __restrict__ W3,
                                                    const float* __restrict__ b3,
                                                    float* __restrict__ out) {
    extern __shared__ char dyn[];
    __half* stg = (__half*)dyn;                       // [4][STG_H]
    float* sh1  = (float*)dyn;                        // overlay after main loop: [64][33]
    float* sW2  = sh1 + 64 * 33;
    float* sb2  = sW2 + 1024;
    float* sW3  = sb2 + 32;
    float* sb3p = sW3 + 32;
    float* spart = sb3p + 1;                          // [256]
    __shared__ int sperm[64];

    const int tile = blockIdx.x;
    const int bk = tile / NTB, i = tile - bk * NTB;
    const int cnt = g_cnt2[bk];
    if (i * 64 >= cnt) return;

    const int tid  = threadIdx.x;
    const int lane = tid & 31, wid = tid >> 5;
    const int wm = wid & 3, wn = wid >> 2;            // 4m x 2n warps; warp tile 16m x 16n

    if (tid < 64) {
        int p = i * 64 + tid;
        sperm[tid] = (p < cnt) ? g_perm[bk * BATCH + p] : -1;
    }
    __syncthreads();

    const int arow = tid >> 2, ac = tid & 3;          // 64 rows x 4 chunks
    int rp = sperm[arow]; if (rp < 0) rp = 0;
    const __half* gA = g_X + (size_t)rp * XW + ac * 8;
    const int brow = (tid >> 2) & 31, bc = tid & 3;   // tid<128: 32 rows x 4 chunks
    const __half* gB = g_W1t + (size_t)brow * 256 + bk * 32 + bc * 8;

    auto issue = [&](int kt) {
        __half* base = stg + (kt & 3) * STG_H;
        asm volatile("cp.async.cg.shared.global [%0], [%1], 16;\n"
                     :: "r"(smem_u32(base + arow * A2STR + ac * 8)), "l"(gA + kt * 32));
        if (tid < 128) {
            asm volatile("cp.async.cg.shared.global [%0], [%1], 16;\n"
                         :: "r"(smem_u32(base + STG_A + brow * A2STR + bc * 8)),
                            "l"(gB + (size_t)kt * 32 * 256));
        }
        asm volatile("cp.async.commit_group;\n");
    };

    float acc[2][4];
    #pragma unroll
    for (int j = 0; j < 2; ++j)
        #pragma unroll
        for (int k = 0; k < 4; ++k) acc[j][k] = 0.f;

    issue(0); issue(1); issue(2);

    const int KT = XW / 32;   // 64
    for (int kt = 0; kt < KT; ++kt) {
        asm volatile("cp.async.wait_group 2;\n");
        __syncthreads();

        const __half* Ab = stg + (kt & 3) * STG_H;
        const __half* Bb = Ab + STG_A;
        #pragma unroll
        for (int ks = 0; ks < 2; ++ks) {
            uint32_t af[4], bf[2][2];
            {
                const __half* p = Ab + (wm * 16 + ((lane >> 3) & 1) * 8 + (lane & 7)) * A2STR
                                     + ks * 16 + (lane >> 4) * 8;
                asm volatile("ldmatrix.sync.aligned.m8n8.x4.shared.b16 {%0,%1,%2,%3}, [%4];\n"
                             : "=r"(af[0]), "=r"(af[1]), "=r"(af[2]), "=r"(af[3])
                             : "r"(smem_u32(p)));
            }
            {
                const __half* p = Bb + (ks * 16 + ((lane >> 3) & 1) * 8 + (lane & 7)) * A2STR
                                     + wn * 16 + (lane >> 4) * 8;
                uint32_t r0, r1, r2, r3;
                asm volatile("ldmatrix.sync.aligned.m8n8.x4.trans.shared.b16 {%0,%1,%2,%3}, [%4];\n"
                             : "=r"(r0), "=r"(r1), "=r"(r2), "=r"(r3) : "r"(smem_u32(p)));
                bf[0][0] = r0; bf[0][1] = r1;
                bf[1][0] = r2; bf[1][1] = r3;
            }
            #pragma unroll
            for (int nf = 0; nf < 2; ++nf)
                asm volatile(
                    "mma.sync.aligned.m16n8k16.row.col.f32.f16.f16.f32 "
                    "{%0,%1,%2,%3}, {%4,%5,%6,%7}, {%8,%9}, {%0,%1,%2,%3};\n"
                    : "+f"(acc[nf][0]), "+f"(acc[nf][1]), "+f"(acc[nf][2]), "+f"(acc[nf][3])
                    : "r"(af[0]), "r"(af[1]), "r"(af[2]), "r"(af[3]),
                      "r"(bf[nf][0]), "r"(bf[nf][1]));
        }

        if (kt + 3 < KT) issue(kt + 3);
        else asm volatile("cp.async.commit_group;\n");
    }

    __syncthreads();   // all stage reads done -> overlay is safe

    // epilogue into overlay + load tail weights
    const int g = lane >> 2, t4 = lane & 3;
    #pragma unroll
    for (int nf = 0; nf < 2; ++nf) {
        const int col = wn * 16 + nf * 8 + 2 * t4;
        #pragma unroll
        for (int h = 0; h < 2; ++h) {
            const int rl = wm * 16 + g + h * 8;
            sh1[rl * 33 + col]     = __saturatef(acc[nf][h * 2 + 0] + b1[bk * 32 + col]);
            sh1[rl * 33 + col + 1] = __saturatef(acc[nf][h * 2 + 1] + b1[bk * 32 + col + 1]);
        }
    }
    for (int idx = tid; idx < 1024; idx += 256) sW2[idx] = W2[bk * 1024 + idx];
    if (tid < 32) { sb2[tid] = b2[bk * 32 + tid]; sW3[tid] = W3[bk * 32 + tid]; }
    if (tid == 0) *sb3p = b3[bk];
    __syncthreads();

    // fused layers 2/3: 4 threads per row, 8 hidden units each
    {
        const int row = tid >> 2, q = tid & 3;
        const float* hr = &sh1[row * 33];
        float o = 0.f;
        #pragma unroll
        for (int ii = q * 8; ii < q * 8 + 8; ++ii) {
            float s = sb2[ii];
            const float* wr = &sW2[ii * 32];
            #pragma unroll
            for (int j = 0; j < 32; ++j) s += wr[j] * hr[j];
            s = __saturatef(s);
            o += sW3[ii] * s;
        }
        spart[tid] = o;
    }
    __syncthreads();
    if (tid < 64) {
        const int r = sperm[tid];
        if (r >= 0) {
            float o = spart[tid * 4] + spart[tid * 4 + 1] + spart[tid * 4 + 2] + spart[tid * 4 + 3];
            o += *sb3p + 0.5f * (g_psqt_s[r] - g_psqt_n[r]);
            out[r] = o;
        }
    }
}

// ---------------- launch ----------------
extern "C" void kernel_launch(void* const* d_in, const int* in_sizes, int n_in,
                              void* d_out, int out_size) {
    const float* stm  = (const float*)d_in[0];
    const float* nstm = (const float*)d_in[1];
    const float* Wacc = (const float*)d_in[2];
    const float* bacc = (const float*)d_in[3];
    const float* W1   = (const float*)d_in[4];
    const float* b1   = (const float*)d_in[5];
    const float* W2   = (const float*)d_in[6];
    const float* b2   = (const float*)d_in[7];
    const float* W3   = (const float*)d_in[8];
    const float* b3   = (const float*)d_in[9];
    float* out = (float*)d_out;

    static bool attr_set = false;
    if (!attr_set) {
        cudaFuncSetAttribute(gemm1_kernel, cudaFuncAttributeMaxDynamicSharedMemorySize, G1_SMEM);
        cudaFuncSetAttribute(gemm2_kernel, cudaFuncAttributeMaxDynamicSharedMemorySize, G2_DYN);
        attr_set = true;
    }

    prep_kernel<<<FEAT_BASE + (2 * BATCH) / 8, 256>>>(stm, nstm, Wacc, W1);

    dim3 g1(18, ACCN / 128);
    gemm1_kernel<<<g1, 512, G1_SMEM>>>(bacc);

    gemm2_kernel<<<MAXT2, 256, G2_DYN>>>(b1, W2, b2, W3, b3, out);
}

// round 14
// speedup vs baseline: 1.0459x; 1.0459x over previous
#include <cuda_runtime.h>
#include <cuda_fp16.h>
#include <cstdint>

#define BATCH 32768
#define NF 162
#define KPAD 176
#define ACCN 1024
#define XW 2048
#define NB 8
#define NTB 40                 // 128-row tile slots per bucket (capacity 5120 rows)
#define MAXT2 (NB * NTB)       // 320 tiles

// ---------------- scratch ----------------
__device__ __half g_F[(size_t)2 * BATCH * KPAD];
__device__ __half g_X[(size_t)BATCH * XW];
__device__ __half g_Wt[(size_t)KPAD * ACCN];         // W_acc^T k-major, zero-padded
__device__ __half g_W1t[XW * 256];                   // W1^T [k][n]
__device__ float  g_psqt_s[BATCH];
__device__ float  g_psqt_n[BATCH];
__device__ int    g_cnt[NB];                         // zero at load; snapshotted+zeroed by gemm1
__device__ int    g_cnt2[NB];                        // stable copy for gemm2
__device__ int    g_perm[NB * BATCH];

__device__ __forceinline__ uint32_t smem_u32(const void* p) {
    return (uint32_t)__cvta_generic_to_shared(p);
}

// ---------------- prep: tiled transposes + feature packing (2 rows/warp) ----------------
#define WACC_BLKS 192
#define W1_BLKS 512
#define FEAT_BASE (WACC_BLKS + W1_BLKS)

__global__ void __launch_bounds__(256) prep_kernel(const float* __restrict__ stm,
                                                   const float* __restrict__ nstm,
                                                   const float* __restrict__ Wacc,
                                                   const float* __restrict__ W1) {
    const int bid = blockIdx.x;
    if (bid < FEAT_BASE) {
        __shared__ float s[32][33];
        const int tx = threadIdx.x & 31, ty = threadIdx.x >> 5;   // 32 x 8
        if (bid < WACC_BLKS) {
            const int j0 = (bid & 31) * 32, k0 = (bid >> 5) * 32;
            #pragma unroll
            for (int r = 0; r < 4; ++r) {
                int j = j0 + ty + r * 8, k = k0 + tx;
                s[ty + r * 8][tx] = (k < NF) ? Wacc[(size_t)j * NF + k] : 0.f;
            }
            __syncthreads();
            #pragma unroll
            for (int r = 0; r < 4; ++r) {
                int k = k0 + ty + r * 8;
                if (k < KPAD) g_Wt[(size_t)k * ACCN + j0 + tx] = __float2half_rn(s[tx][ty + r * 8]);
            }
        } else {
            const int q = bid - WACC_BLKS;
            const int n0 = (q & 7) * 32, k0 = (q >> 3) * 32;
            #pragma unroll
            for (int r = 0; r < 4; ++r)
                s[ty + r * 8][tx] = W1[(size_t)(n0 + ty + r * 8) * XW + k0 + tx];
            __syncthreads();
            #pragma unroll
            for (int r = 0; r < 4; ++r)
                g_W1t[(size_t)(k0 + ty + r * 8) * 256 + n0 + tx] =
                    __float2half_rn(s[tx][ty + r * 8]);
        }
        return;
    }
    // feature part: one warp handles stm row w AND nstm row w
    int w = ((bid - FEAT_BASE) * 256 + threadIdx.x) >> 5;
    int lane = threadIdx.x & 31;
    if (w >= BATCH) return;
    const float2* WaccLast = (const float2*)(Wacc + (size_t)ACCN * NF);
    const float2* srcs = (const float2*)(stm  + (size_t)w * NF);
    const float2* srcn = (const float2*)(nstm + (size_t)w * NF);
    __half2* dsts = (__half2*)(g_F + (size_t)w * KPAD);
    __half2* dstn = (__half2*)(g_F + (size_t)(BATCH + w) * KPAD);

    float cnt = 0.f, pss = 0.f, psn = 0.f;
    #pragma unroll
    for (int it = 0; it < 3; ++it) {
        int p = lane + it * 32;                      // KPAD/2 = 88 pairs
        if (p < 88) {
            float sx = 0.f, sy = 0.f, nx = 0.f, ny = 0.f;
            if (p < 81) {
                float2 vs = srcs[p];
                float2 vn = srcn[p];
                float2 wl = WaccLast[p];
                sx = vs.x; sy = vs.y; nx = vn.x; ny = vn.y;
                pss += sx * wl.x + sy * wl.y;
                psn += nx * wl.x + ny * wl.y;
                cnt += sx + sy;
            }
            dsts[p] = __floats2half2_rn(sx, sy);
            dstn[p] = __floats2half2_rn(nx, ny);
        }
    }
    #pragma unroll
    for (int o = 16; o; o >>= 1) {
        cnt += __shfl_xor_sync(0xffffffffu, cnt, o);
        pss += __shfl_xor_sync(0xffffffffu, pss, o);
        psn += __shfl_xor_sync(0xffffffffu, psn, o);
    }
    if (lane == 0) {
        int pc = (int)(cnt + 0.5f);
        int b  = pc / 20;
        b = (b > NB - 1) ? NB - 1 : b;
        int pos = atomicAdd(&g_cnt[b], 1);
        g_perm[b * BATCH + pos] = w;
        g_psqt_s[w] = pss;
        g_psqt_n[w] = psn;
    }
}

// ---------------- GEMM1: 512 thr, BN=256, B-resident, full-tile A double buffer ----------------
#define BSTR2 264   // 256 + 8 pad
#define ASTR 184    // 176 + 8 pad
#define G1_SMEM ((KPAD * BSTR2 + 2 * 128 * ASTR) * 2)   // 187,136 bytes

__global__ void __launch_bounds__(512) gemm1_kernel(const float* __restrict__ bias) {
    extern __shared__ __half sh[];
    __half* Bs = sh;                       // [176][BSTR2]
    __half* As = sh + KPAD * BSTR2;        // [2][128][ASTR]

    const int tid  = threadIdx.x;
    const int lane = tid & 31, wid = tid >> 5;
    const int wm = wid & 3, wn = wid >> 2;          // 4m x 4n warps; warp tile 32m x 64n
    const int n0 = blockIdx.y * 256;
    const int mslot = blockIdx.x;                   // 0..35

    if (blockIdx.x == 0 && blockIdx.y == 0 && tid < NB) {
        g_cnt2[tid] = g_cnt[tid];                   // snapshot for gemm2
        g_cnt[tid] = 0;                             // clean state for next replay
    }

    // resident B: 176 rows x 32 chunks of 16B
    for (int idx = tid; idx < KPAD * 32; idx += 512) {
        int k = idx >> 5, c = idx & 31;
        asm volatile("cp.async.cg.shared.global [%0], [%1], 16;\n"
                     :: "r"(smem_u32(Bs + k * BSTR2 + c * 8)),
                        "l"(g_Wt + (size_t)k * ACCN + n0 + c * 8));
    }

    auto loadA = [&](int buf, int mt) {
        const __half* base = g_F + (size_t)mt * 128 * KPAD;
        __half* dst = As + buf * (128 * ASTR);
        #pragma unroll
        for (int it = 0; it < 6; ++it) {
            int idx = tid + it * 512;                // 128 x 22 chunks
            if (idx < 128 * 22) {
                int r = idx / 22, c = idx - r * 22;
                asm volatile("cp.async.cg.shared.global [%0], [%1], 16;\n"
                             :: "r"(smem_u32(dst + r * ASTR + c * 8)),
                                "l"(base + (size_t)r * KPAD + c * 8));
            }
        }
    };

    loadA(0, mslot);
    asm volatile("cp.async.commit_group;\n");
    const int jmax = (512 - mslot + 35) / 36;
    if (jmax > 1) loadA(1, mslot + 36);
    asm volatile("cp.async.commit_group;\n");

    const int g = lane >> 2, t4 = lane & 3;
    int buf = 0;
    for (int j = 0; j < jmax; ++j) {
        const int mt = mslot + j * 36;
        asm volatile("cp.async.wait_group 1;\n");
        __syncthreads();

        float acc[2][8][4];
        #pragma unroll
        for (int i = 0; i < 2; ++i)
            #pragma unroll
            for (int jj = 0; jj < 8; ++jj)
                #pragma unroll
                for (int k = 0; k < 4; ++k) acc[i][jj][k] = 0.f;

        const __half* Ab = As + buf * (128 * ASTR);
        #pragma unroll
        for (int kt = 0; kt < 11; ++kt) {
            uint32_t af[2][4], bf[8][2];
            #pragma unroll
            for (int mf = 0; mf < 2; ++mf) {
                const __half* p = Ab + (wm * 32 + mf * 16 + ((lane >> 3) & 1) * 8 + (lane & 7)) * ASTR
                                     + kt * 16 + (lane >> 4) * 8;
                asm volatile("ldmatrix.sync.aligned.m8n8.x4.shared.b16 {%0,%1,%2,%3}, [%4];\n"
                             : "=r"(af[mf][0]), "=r"(af[mf][1]), "=r"(af[mf][2]), "=r"(af[mf][3])
                             : "r"(smem_u32(p)));
            }
            #pragma unroll
            for (int ng = 0; ng < 4; ++ng) {
                const __half* p = Bs + (kt * 16 + ((lane >> 3) & 1) * 8 + (lane & 7)) * BSTR2
                                     + wn * 64 + ng * 16 + (lane >> 4) * 8;
                uint32_t r0, r1, r2, r3;
                asm volatile("ldmatrix.sync.aligned.m8n8.x4.trans.shared.b16 {%0,%1,%2,%3}, [%4];\n"
                             : "=r"(r0), "=r"(r1), "=r"(r2), "=r"(r3) : "r"(smem_u32(p)));
                bf[ng * 2 + 0][0] = r0; bf[ng * 2 + 0][1] = r1;
                bf[ng * 2 + 1][0] = r2; bf[ng * 2 + 1][1] = r3;
            }
            #pragma unroll
            for (int mf = 0; mf < 2; ++mf)
                #pragma unroll
                for (int nf = 0; nf < 8; ++nf)
                    asm volatile(
                        "mma.sync.aligned.m16n8k16.row.col.f32.f16.f16.f32 "
                        "{%0,%1,%2,%3}, {%4,%5,%6,%7}, {%8,%9}, {%0,%1,%2,%3};\n"
                        : "+f"(acc[mf][nf][0]), "+f"(acc[mf][nf][1]),
                          "+f"(acc[mf][nf][2]), "+f"(acc[mf][nf][3])
                        : "r"(af[mf][0]), "r"(af[mf][1]), "r"(af[mf][2]), "r"(af[mf][3]),
                          "r"(bf[nf][0]), "r"(bf[nf][1]));
        }
        __syncthreads();

        if (j + 2 < jmax) loadA(buf, mslot + (j + 2) * 36);
        asm volatile("cp.async.commit_group;\n");

        // epilogue: bias + clip^2 -> g_X
        #pragma unroll
        for (int mf = 0; mf < 2; ++mf) {
            #pragma unroll
            for (int nf = 0; nf < 8; ++nf) {
                const int col = n0 + wn * 64 + nf * 8 + 2 * t4;
                #pragma unroll
                for (int h = 0; h < 2; ++h) {
                    const int row = mt * 128 + wm * 32 + mf * 16 + g + h * 8;
                    float v0 = __saturatef(acc[mf][nf][h * 2 + 0] + bias[col]);     v0 *= v0;
                    float v1 = __saturatef(acc[mf][nf][h * 2 + 1] + bias[col + 1]); v1 *= v1;
                    const size_t off = (row < BATCH)
                        ? (size_t)row * XW + col
                        : (size_t)(row - BATCH) * XW + ACCN + col;
                    *(__half2*)(g_X + off) = __floats2half2_rn(v0, v1);
                }
            }
        }
        buf ^= 1;
    }
}

// ---------------- GEMM2: 128-row tiles, BK=32, 4-stage ring, fused tail (proven 47us) ----------------
#define A2STR 40
#define STG_A (128 * A2STR)
#define STG_B (32 * A2STR)
#define STG_H (STG_A + STG_B)
#define G2_DYN (4 * STG_H * 2)     // 51200 bytes; overlay (21.3 KB) fits inside

__global__ void __launch_bounds__(256) gemm2_kernel(const float* __restrict__ b1,
                                                    const float* __restrict__ W2,
                                                    const float* __restrict__ b2,
                                                    const float* __restrict__ W3,
                                                    const float* __restrict__ b3,
                                                    float* __restrict__ out) {
    extern __shared__ char dyn[];
    __half* stg = (__half*)dyn;                       // [4][STG_H]
    float* sh1  = (float*)dyn;                        // overlay after main loop
    float* sW2  = sh1 + 128 * 33;
    float* sb2  = sW2 + 1024;
    float* sW3  = sb2 + 32;
    float* sb3p = sW3 + 32;
    __shared__ int sperm[128];

    const int bk = blockIdx.x / NTB, i = blockIdx.x - bk * NTB;
    const int cnt = g_cnt2[bk];
    if (i * 128 >= cnt) return;

    const int tid  = threadIdx.x;
    const int lane = tid & 31, wid = tid >> 5;
    const int wm = wid & 3, wn = wid >> 2;            // warp tile 32m x 16n

    if (tid < 128) {
        int p = i * 128 + tid;
        sperm[tid] = (p < cnt) ? g_perm[bk * BATCH + p] : -1;
    }
    __syncthreads();

    const int arow = tid >> 1;
    const int ac2  = (tid & 1) * 2;
    int rp = sperm[arow]; if (rp < 0) rp = 0;
    const __half* gA = g_X + (size_t)rp * XW + ac2 * 8;
    const int brow = tid >> 2, bc = tid & 3;
    const __half* gB = g_W1t + (size_t)brow * 256 + bk * 32 + bc * 8;

    auto issue = [&](int kt) {
        __half* base = stg + (kt & 3) * STG_H;
        uint32_t sa = smem_u32(base + arow * A2STR + ac2 * 8);
        #pragma unroll
        for (int c = 0; c < 2; ++c)
            asm volatile("cp.async.cg.shared.global [%0], [%1], 16;\n"
                         :: "r"(sa + c * 16), "l"(gA + kt * 32 + c * 8));
        if (tid < 128) {
            uint32_t sb = smem_u32(base + STG_A + brow * A2STR + bc * 8);
            asm volatile("cp.async.cg.shared.global [%0], [%1], 16;\n"
                         :: "r"(sb), "l"(gB + (size_t)kt * 32 * 256));
        }
        asm volatile("cp.async.commit_group;\n");
    };

    float acc[2][2][4];
    #pragma unroll
    for (int i2 = 0; i2 < 2; ++i2)
        #pragma unroll
        for (int j = 0; j < 2; ++j)
            #pragma unroll
            for (int k = 0; k < 4; ++k) acc[i2][j][k] = 0.f;

    issue(0); issue(1); issue(2);

    const int KT = XW / 32;   // 64
    for (int kt = 0; kt < KT; ++kt) {
        asm volatile("cp.async.wait_group 2;\n");
        __syncthreads();

        const __half* Ab = stg + (kt & 3) * STG_H;
        const __half* Bb = Ab + STG_A;
        #pragma unroll
        for (int ks = 0; ks < 2; ++ks) {
            uint32_t af[2][4], bf[2][2];
            #pragma unroll
            for (int mf = 0; mf < 2; ++mf) {
                const __half* p = Ab + (wm * 32 + mf * 16 + ((lane >> 3) & 1) * 8 + (lane & 7)) * A2STR
                                     + ks * 16 + (lane >> 4) * 8;
                asm volatile("ldmatrix.sync.aligned.m8n8.x4.shared.b16 {%0,%1,%2,%3}, [%4];\n"
                             : "=r"(af[mf][0]), "=r"(af[mf][1]), "=r"(af[mf][2]), "=r"(af[mf][3])
                             : "r"(smem_u32(p)));
            }
            {
                const __half* p = Bb + (ks * 16 + ((lane >> 3) & 1) * 8 + (lane & 7)) * A2STR
                                     + wn * 16 + (lane >> 4) * 8;
                uint32_t r0, r1, r2, r3;
                asm volatile("ldmatrix.sync.aligned.m8n8.x4.trans.shared.b16 {%0,%1,%2,%3}, [%4];\n"
                             : "=r"(r0), "=r"(r1), "=r"(r2), "=r"(r3) : "r"(smem_u32(p)));
                bf[0][0] = r0; bf[0][1] = r1;
                bf[1][0] = r2; bf[1][1] = r3;
            }
            #pragma unroll
            for (int mf = 0; mf < 2; ++mf)
                #pragma unroll
                for (int nf = 0; nf < 2; ++nf)
                    asm volatile(
                        "mma.sync.aligned.m16n8k16.row.col.f32.f16.f16.f32 "
                        "{%0,%1,%2,%3}, {%4,%5,%6,%7}, {%8,%9}, {%0,%1,%2,%3};\n"
                        : "+f"(acc[mf][nf][0]), "+f"(acc[mf][nf][1]),
                          "+f"(acc[mf][nf][2]), "+f"(acc[mf][nf][3])
                        : "r"(af[mf][0]), "r"(af[mf][1]), "r"(af[mf][2]), "r"(af[mf][3]),
                          "r"(bf[nf][0]), "r"(bf[nf][1]));
        }

        if (kt + 3 < KT) issue(kt + 3);
        else asm volatile("cp.async.commit_group;\n");
    }

    __syncthreads();   // all stage reads done -> overlay is safe

    // epilogue into overlay + load tail weights
    const int g = lane >> 2, t4 = lane & 3;
    #pragma unroll
    for (int mf = 0; mf < 2; ++mf) {
        #pragma unroll
        for (int nf = 0; nf < 2; ++nf) {
            const int col = wn * 16 + nf * 8 + 2 * t4;
            #pragma unroll
            for (int h = 0; h < 2; ++h) {
                const int rl = wm * 32 + mf * 16 + g + h * 8;
                sh1[rl * 33 + col]     = __saturatef(acc[mf][nf][h * 2 + 0] + b1[bk * 32 + col]);
                sh1[rl * 33 + col + 1] = __saturatef(acc[mf][nf][h * 2 + 1] + b1[bk * 32 + col + 1]);
            }
        }
    }
    for (int idx = tid; idx < 1024; idx += 256) sW2[idx] = W2[bk * 1024 + idx];
    if (tid < 32) { sb2[tid] = b2[bk * 32 + tid]; sW3[tid] = W3[bk * 32 + tid]; }
    if (tid == 0) *sb3p = b3[bk];
    __syncthreads();

    if (tid < 128) {
        const int r = sperm[tid];
        if (r >= 0) {
            const float* hr = &sh1[tid * 33];
            float o = 0.f;
            #pragma unroll 4
            for (int ii = 0; ii < 32; ++ii) {
                float s = sb2[ii];
                const float* wr = &sW2[ii * 32];
                #pragma unroll
                for (int j = 0; j < 32; ++j) s += wr[j] * hr[j];
                s = __saturatef(s);
                o += sW3[ii] * s;
            }
            o += *sb3p + 0.5f * (g_psqt_s[r] - g_psqt_n[r]);
            out[r] = o;
        }
    }
}

// ---------------- launch ----------------
extern "C" void kernel_launch(void* const* d_in, const int* in_sizes, int n_in,
                              void* d_out, int out_size) {
    const float* stm  = (const float*)d_in[0];
    const float* nstm = (const float*)d_in[1];
    const float* Wacc = (const float*)d_in[2];
    const float* bacc = (const float*)d_in[3];
    const float* W1   = (const float*)d_in[4];
    const float* b1   = (const float*)d_in[5];
    const float* W2   = (const float*)d_in[6];
    const float* b2   = (const float*)d_in[7];
    const float* W3   = (const float*)d_in[8];
    const float* b3   = (const float*)d_in[9];
    float* out = (float*)d_out;

    static bool attr_set = false;
    if (!attr_set) {
        cudaFuncSetAttribute(gemm1_kernel, cudaFuncAttributeMaxDynamicSharedMemorySize, G1_SMEM);
        cudaFuncSetAttribute(gemm2_kernel, cudaFuncAttributeMaxDynamicSharedMemorySize, G2_DYN);
        attr_set = true;
    }

    prep_kernel<<<FEAT_BASE + BATCH / 8, 256>>>(stm, nstm, Wacc, W1);

    dim3 g1(36, ACCN / 256);
    gemm1_kernel<<<g1, 512, G1_SMEM>>>(bacc);

    gemm2_kernel<<<MAXT2, 256, G2_DYN>>>(b1, W2, b2, W3, b3, out);
}